// round 12
// baseline (speedup 1.0000x reference)
#include <cuda_runtime.h>
#include <cuda_bf16.h>
#include <math.h>
#include <stdint.h>

#define FULL 0xffffffffu

// Problem constants
#define Bz 2
#define Sdim 2048
#define Edim 256
#define Hn 8
#define HD 32
#define WIN 129
#define OFF 64
#define MTOK (Bz*Sdim)          // 4096 token rows
#define KW 128                  // packed k-words per 256 floats
#define WPK (128*256)           // u32 words per packed weight matrix

// Scratch (no cudaMalloc allowed)
__device__ uint32_t g_xh[MTOK*KW];   // x+pe, bf16 hi, k-packed pairs
__device__ uint32_t g_xl[MTOK*KW];   // bf16 lo
__device__ float    g_q[MTOK*Edim];
__device__ float    g_k[MTOK*Edim];
__device__ float    g_v[MTOK*Edim];
__device__ uint32_t g_ch[MTOK*KW];   // ctx bf16 hi packed
__device__ uint32_t g_cl[MTOK*KW];   // ctx bf16 lo packed
__device__ uint32_t g_wh[4*WPK];     // Wq,Wk,Wv,Wo packed [kp][n] bf16 hi
__device__ uint32_t g_wl[4*WPK];     // lo

// ---------------------------------------------------------------------------
// helpers
// ---------------------------------------------------------------------------
__device__ __forceinline__ void split_bf16(float x, uint16_t& h, uint16_t& l) {
    __nv_bfloat16 bh = __float2bfloat16_rn(x);
    float r = x - __bfloat162float(bh);
    __nv_bfloat16 bl = __float2bfloat16_rn(r);
    h = __bfloat16_as_ushort(bh);
    l = __bfloat16_as_ushort(bl);
}
__device__ __forceinline__ uint32_t pack2(uint16_t e0, uint16_t e1) {
    return (uint32_t)e0 | ((uint32_t)e1 << 16);
}
__device__ __forceinline__ void split_pack2(float x0, float x1,
                                            uint32_t& wh, uint32_t& wl) {
    uint16_t h0, l0, h1, l1;
    split_bf16(x0, h0, l0);
    split_bf16(x1, h1, l1);
    wh = pack2(h0, h1);
    wl = pack2(l0, l1);
}
__device__ __forceinline__ float bf16_half_to_f(uint32_t w, int half) {
    uint16_t u = half ? (uint16_t)(w >> 16) : (uint16_t)(w & 0xffff);
    return __bfloat162float(__ushort_as_bfloat16(u));
}
__device__ __forceinline__ void mma_bf16(float* acc, const uint32_t* a, const uint32_t* b) {
    asm volatile(
        "mma.sync.aligned.m16n8k16.row.col.f32.bf16.bf16.f32 "
        "{%0,%1,%2,%3}, {%4,%5,%6,%7}, {%8,%9}, {%0,%1,%2,%3};\n"
        : "+f"(acc[0]), "+f"(acc[1]), "+f"(acc[2]), "+f"(acc[3])
        : "r"(a[0]), "r"(a[1]), "r"(a[2]), "r"(a[3]), "r"(b[0]), "r"(b[1]));
}
__device__ __forceinline__ void cp16(void* smem, const void* g) {
    uint32_t s = (uint32_t)__cvta_generic_to_shared(smem);
    asm volatile("cp.async.cg.shared.global [%0], [%1], 16;\n" :: "r"(s), "l"(g));
}

// ---------------------------------------------------------------------------
// x + PE -> packed bf16 hi/lo pairs (one thread per k-pair)
// ---------------------------------------------------------------------------
__global__ void add_pe_pack_kernel(const float* __restrict__ x,
                                   uint32_t* __restrict__ yh,
                                   uint32_t* __restrict__ yl) {
    int i = blockIdx.x * 256 + threadIdx.x;   // MTOK*KW threads
    int e2 = i & (KW - 1);                    // pair index = e>>1
    int m  = i >> 7;
    int s  = m & (Sdim - 1);
    float dv = expf((float)e2 * (-2.0f * 9.210340371976184f / 256.0f));
    float ang = (float)s * dv;
    float2 xv = *(const float2*)&x[m * Edim + 2 * e2];
    uint32_t wh, wl;
    split_pack2(xv.x + sinf(ang), xv.y + cosf(ang), wh, wl);
    yh[i] = wh;
    yl[i] = wl;
}

// ---------------------------------------------------------------------------
// Pack the 4 weight matrices: word [kp][n] = (W[2kp][n], W[2kp+1][n]) bf16
// ---------------------------------------------------------------------------
__global__ void pack_w_kernel(const float* __restrict__ Wq, const float* __restrict__ Wk,
                              const float* __restrict__ Wv, const float* __restrict__ Wo,
                              uint32_t* __restrict__ wh, uint32_t* __restrict__ wl) {
    int i = blockIdx.x * 256 + threadIdx.x;     // 4*WPK threads
    int wsel = i >> 15;
    int r    = i & (WPK - 1);
    int kp   = r >> 8;
    int n    = r & 255;
    const float* W = (wsel == 0) ? Wq : ((wsel == 1) ? Wk : ((wsel == 2) ? Wv : Wo));
    uint32_t hw, lw;
    split_pack2(W[(2 * kp) * Edim + n], W[(2 * kp + 1) * Edim + n], hw, lw);
    wh[i] = hw;
    wl[i] = lw;
}

// ---------------------------------------------------------------------------
// 3xBF16 tensor-core GEMM (unchanged from R11).
// ---------------------------------------------------------------------------
#define GBM 64
#define GBN 64
#define NSTAGE 4
#define PA 12
#define PB 72

__global__ __launch_bounds__(128) void gemm_tc_kernel(
    const uint32_t* __restrict__ Xh, const uint32_t* __restrict__ Xl,
    const uint32_t* __restrict__ Whb, const uint32_t* __restrict__ Wlb,
    const float* __restrict__ b0, float* __restrict__ Y0,
    const float* __restrict__ b1, float* __restrict__ Y1,
    const float* __restrict__ b2, float* __restrict__ Y2)
{
    __shared__ uint32_t Ahs[NSTAGE][GBM][PA];
    __shared__ uint32_t Als[NSTAGE][GBM][PA];
    __shared__ uint32_t Bhs[NSTAGE][8][PB];
    __shared__ uint32_t Bls[NSTAGE][8][PB];

    const int t    = threadIdx.x;
    const int lane = t & 31;
    const int warp = t >> 5;
    const int warp_m = warp & 1;
    const int warp_n = warp >> 1;
    const int lr = lane >> 2;
    const int lc = lane & 3;

    const int bm = blockIdx.x * GBM;
    const int wsel = blockIdx.y >> 2;
    const int bn = (blockIdx.y & 3) * GBN;

    const uint32_t* Wh = Whb + wsel * WPK;
    const uint32_t* Wl = Wlb + wsel * WPK;
    const float* bias  = (wsel == 0) ? b0 : ((wsel == 1) ? b1 : b2);
    float*       Y     = (wsel == 0) ? Y0 : ((wsel == 1) ? Y1 : Y2);

    float acc[2][4][4];
#pragma unroll
    for (int mf = 0; mf < 2; ++mf)
#pragma unroll
        for (int nf = 0; nf < 4; ++nf)
#pragma unroll
            for (int r = 0; r < 4; ++r) acc[mf][nf][r] = 0.f;

    const int am  = t >> 1;
    const int aq  = (t & 1) * 4;
    const int br  = t >> 4;
    const int bq  = (t & 15) * 4;

#define LOAD_TILE(it, buf)                                                     \
    do {                                                                       \
        int kw0 = (it) * 8;                                                    \
        cp16(&Ahs[buf][am][aq], &Xh[(bm + am) * KW + kw0 + aq]);               \
        cp16(&Als[buf][am][aq], &Xl[(bm + am) * KW + kw0 + aq]);               \
        cp16(&Bhs[buf][br][bq], &Wh[(kw0 + br) * Edim + bn + bq]);             \
        cp16(&Bls[buf][br][bq], &Wl[(kw0 + br) * Edim + bn + bq]);             \
        asm volatile("cp.async.commit_group;\n");                              \
    } while (0)

    const int KITERS = 16;
    LOAD_TILE(0, 0);
    LOAD_TILE(1, 1);
    LOAD_TILE(2, 2);

    for (int it = 0; it < KITERS; ++it) {
        const int buf = it & (NSTAGE - 1);
        const int rem = KITERS - 1 - it;
        if (rem >= 2)      asm volatile("cp.async.wait_group 2;\n");
        else if (rem == 1) asm volatile("cp.async.wait_group 1;\n");
        else               asm volatile("cp.async.wait_group 0;\n");
        __syncthreads();

        if (it + 3 < KITERS) LOAD_TILE(it + 3, (it + 3) & (NSTAGE - 1));

        uint32_t ah[2][4], al[2][4], bh[4][2], bl[4][2];
#pragma unroll
        for (int mf = 0; mf < 2; ++mf) {
            int r = warp_m * 32 + mf * 16 + lr;
            ah[mf][0] = Ahs[buf][r][lc];
            ah[mf][1] = Ahs[buf][r + 8][lc];
            ah[mf][2] = Ahs[buf][r][lc + 4];
            ah[mf][3] = Ahs[buf][r + 8][lc + 4];
            al[mf][0] = Als[buf][r][lc];
            al[mf][1] = Als[buf][r + 8][lc];
            al[mf][2] = Als[buf][r][lc + 4];
            al[mf][3] = Als[buf][r + 8][lc + 4];
        }
#pragma unroll
        for (int nf = 0; nf < 4; ++nf) {
            int cn = warp_n * 32 + nf * 8 + lr;
            bh[nf][0] = Bhs[buf][lc][cn];
            bh[nf][1] = Bhs[buf][lc + 4][cn];
            bl[nf][0] = Bls[buf][lc][cn];
            bl[nf][1] = Bls[buf][lc + 4][cn];
        }
#pragma unroll
        for (int mf = 0; mf < 2; ++mf)
#pragma unroll
            for (int nf = 0; nf < 4; ++nf) {
                mma_bf16(acc[mf][nf], al[mf], bh[nf]);
                mma_bf16(acc[mf][nf], ah[mf], bl[nf]);
                mma_bf16(acc[mf][nf], ah[mf], bh[nf]);
            }
        __syncthreads();
    }

#pragma unroll
    for (int mf = 0; mf < 2; ++mf) {
        int r = bm + warp_m * 32 + mf * 16 + lr;
#pragma unroll
        for (int nf = 0; nf < 4; ++nf) {
            int cg = bn + warp_n * 32 + nf * 8 + 2 * lc;
            float bv0 = bias[cg], bv1 = bias[cg + 1];
            float2 v0 = make_float2(acc[mf][nf][0] + bv0, acc[mf][nf][1] + bv1);
            float2 v1 = make_float2(acc[mf][nf][2] + bv0, acc[mf][nf][3] + bv1);
            *(float2*)&Y[r * Edim + cg] = v0;
            *(float2*)&Y[(r + 8) * Edim + cg] = v1;
        }
    }
#undef LOAD_TILE
}

// ---------------------------------------------------------------------------
// Tensor-core windowed attention, 3xBF16 m16n8k16, splits hoisted to staging.
// Block: 256 thr (8 warps), 32 queries per (b,h). Key rows 160.
// Smem layouts (u32 words, bf16x2 packed along the k-dim of each MMA):
//   kd[dword][key]   stride 168  (QK^T B operand)
//   vk[kword][dim]   stride 40   (P@V  B operand)
//   qp[row][dword]   stride 20   (QK^T A operand)
//   pp[row][kword]   stride 84   (P@V  A operand)
// ---------------------------------------------------------------------------
#define KSTR 168
#define VSTR 40
#define QSTR 20
#define PSTR 84
#define NROWS 160

#define SM_KH 0
#define SM_KL (SM_KH + 16*KSTR)            // 2688
#define SM_VH (SM_KL + 16*KSTR)            // 5376
#define SM_VL (SM_VH + 80*VSTR)            // 8576
#define SM_QH (SM_VL + 80*VSTR)            // 11776
#define SM_QL (SM_QH + 32*QSTR)            // 12416
#define SM_PH (SM_QL + 32*QSTR)            // 13056
#define SM_PL (SM_PH + 32*PSTR)            // 15744
#define SM_RMAX (SM_PL + 32*PSTR)          // 18432
#define SM_RSUM (SM_RMAX + 128)            // 18560
#define SM_TOT (SM_RSUM + 128)             // 18688 u32 = 74752 B

__global__ __launch_bounds__(256) void attn_kernel(
    const float* __restrict__ q, const float* __restrict__ k,
    const float* __restrict__ v,
    uint32_t* __restrict__ ctx_h, uint32_t* __restrict__ ctx_l,
    float* __restrict__ attn_out)
{
    extern __shared__ uint32_t smu[];
    uint32_t* khs = smu + SM_KH;
    uint32_t* kls = smu + SM_KL;
    uint32_t* vhs = smu + SM_VH;
    uint32_t* vls = smu + SM_VL;
    uint32_t* qhs = smu + SM_QH;
    uint32_t* qls = smu + SM_QL;
    uint32_t* phs = smu + SM_PH;
    uint32_t* pls = smu + SM_PL;
    float* rmax = (float*)(smu + SM_RMAX);
    float* rsum = (float*)(smu + SM_RSUM);

    const int b    = blockIdx.z;
    const int h    = blockIdx.y;
    const int s0   = blockIdx.x * 32;
    const int t    = threadIdx.x;
    const int lane = t & 31;
    const int warp = t >> 5;
    const int warp_m = warp & 1;
    const int warp_n = warp >> 1;
    const int lr = lane >> 2;
    const int lc = lane & 3;

    const int base = (b * Sdim) * Edim + h * HD;

    // ---- stage K: [dword][key], split to bf16 hi/lo ----
    for (int i = t; i < NROWS * 16; i += 256) {
        int r  = i >> 4;
        int dw = i & 15;
        int tok = min(max(s0 - OFF + r, 0), Sdim - 1);
        float2 kv = *(const float2*)&k[base + tok * Edim + 2 * dw];
        uint32_t hw, lw;
        split_pack2(kv.x, kv.y, hw, lw);
        khs[dw * KSTR + r] = hw;
        kls[dw * KSTR + r] = lw;
    }
    // ---- stage V: [kword][dim] ----
    for (int i = t; i < 80 * 32; i += 256) {
        int kw  = i >> 5;
        int dim = i & 31;
        int tok0 = min(max(s0 - OFF + 2 * kw, 0), Sdim - 1);
        int tok1 = min(max(s0 - OFF + 2 * kw + 1, 0), Sdim - 1);
        float v0 = v[base + tok0 * Edim + dim];
        float v1 = v[base + tok1 * Edim + dim];
        uint32_t hw, lw;
        split_pack2(v0, v1, hw, lw);
        vhs[kw * VSTR + dim] = hw;
        vls[kw * VSTR + dim] = lw;
    }
    // ---- stage Q: [row][dword] ----
    for (int i = t; i < 32 * 16; i += 256) {
        int row = i >> 4;
        int dw  = i & 15;
        float2 qv = *(const float2*)&q[base + (s0 + row) * Edim + 2 * dw];
        uint32_t hw, lw;
        split_pack2(qv.x, qv.y, hw, lw);
        qhs[row * QSTR + dw] = hw;
        qls[row * QSTR + dw] = lw;
    }
    __syncthreads();

    // ---- scores: per warp S[16 q][40 keys] = 5 n-tiles x 2 k16-steps ----
    const int q0 = warp_m * 16 + lr;
    const int q1 = q0 + 8;

    float acc[5][4];
#pragma unroll
    for (int nt = 0; nt < 5; ++nt)
#pragma unroll
        for (int j = 0; j < 4; ++j) acc[nt][j] = 0.f;

#pragma unroll
    for (int s = 0; s < 2; ++s) {
        uint32_t ah[4], al[4];
        ah[0] = qhs[q0 * QSTR + s * 8 + lc];
        ah[1] = qhs[q1 * QSTR + s * 8 + lc];
        ah[2] = qhs[q0 * QSTR + s * 8 + lc + 4];
        ah[3] = qhs[q1 * QSTR + s * 8 + lc + 4];
        al[0] = qls[q0 * QSTR + s * 8 + lc];
        al[1] = qls[q1 * QSTR + s * 8 + lc];
        al[2] = qls[q0 * QSTR + s * 8 + lc + 4];
        al[3] = qls[q1 * QSTR + s * 8 + lc + 4];
#pragma unroll
        for (int nt = 0; nt < 5; ++nt) {
            int key = warp_n * 40 + nt * 8 + lr;
            uint32_t bh[2], bl[2];
            bh[0] = khs[(s * 8 + lc) * KSTR + key];
            bh[1] = khs[(s * 8 + lc + 4) * KSTR + key];
            bl[0] = kls[(s * 8 + lc) * KSTR + key];
            bl[1] = kls[(s * 8 + lc + 4) * KSTR + key];
            mma_bf16(acc[nt], al, bh);
            mma_bf16(acc[nt], ah, bl);
            mma_bf16(acc[nt], ah, bh);
        }
    }

    // ---- scale + band/sequence mask; row maxima ----
    const float scale = 0.17677669529663689f;  // 1/sqrt(32)
    float m0 = -INFINITY, m1 = -INFINITY;
#pragma unroll
    for (int nt = 0; nt < 5; ++nt) {
#pragma unroll
        for (int j = 0; j < 4; ++j) {
            int row = (j >= 2) ? q1 : q0;
            int key = warp_n * 40 + nt * 8 + 2 * lc + (j & 1);
            int w  = key - row;
            int kg = s0 - OFF + key;
            bool valid = (w >= 0) & (w <= 128) & (kg >= 0) & (kg < Sdim);
            float s = valid ? acc[nt][j] * scale : -1e9f;
            acc[nt][j] = s;
            if (j >= 2) m1 = fmaxf(m1, s); else m0 = fmaxf(m0, s);
        }
    }
    m0 = fmaxf(m0, __shfl_xor_sync(FULL, m0, 1));
    m0 = fmaxf(m0, __shfl_xor_sync(FULL, m0, 2));
    m1 = fmaxf(m1, __shfl_xor_sync(FULL, m1, 1));
    m1 = fmaxf(m1, __shfl_xor_sync(FULL, m1, 2));
    if (lc == 0) { rmax[q0 * 4 + warp_n] = m0; rmax[q1 * 4 + warp_n] = m1; }
    __syncthreads();

    float4 t0 = *(const float4*)&rmax[q0 * 4];
    float4 t1 = *(const float4*)&rmax[q1 * 4];
    float gm0 = fmaxf(fmaxf(t0.x, t0.y), fmaxf(t0.z, t0.w));
    float gm1 = fmaxf(fmaxf(t1.x, t1.y), fmaxf(t1.z, t1.w));

    float sum0 = 0.f, sum1 = 0.f;
#pragma unroll
    for (int nt = 0; nt < 5; ++nt) {
#pragma unroll
        for (int j = 0; j < 4; ++j) {
            float e = expf(acc[nt][j] - ((j >= 2) ? gm1 : gm0));
            acc[nt][j] = e;
            if (j >= 2) sum1 += e; else sum0 += e;
        }
    }
    sum0 += __shfl_xor_sync(FULL, sum0, 1);
    sum0 += __shfl_xor_sync(FULL, sum0, 2);
    sum1 += __shfl_xor_sync(FULL, sum1, 1);
    sum1 += __shfl_xor_sync(FULL, sum1, 2);
    if (lc == 0) { rsum[q0 * 4 + warp_n] = sum0; rsum[q1 * 4 + warp_n] = sum1; }
    __syncthreads();

    float4 u0 = *(const float4*)&rsum[q0 * 4];
    float4 u1 = *(const float4*)&rsum[q1 * 4];
    float inv0 = 1.f / (u0.x + u0.y + u0.z + u0.w);
    float inv1 = 1.f / (u1.x + u1.y + u1.z + u1.w);

    // ---- normalized P -> packed bf16 hi/lo smem (keys 2lc,2lc+1 = one word) ----
#pragma unroll
    for (int nt = 0; nt < 5; ++nt) {
        int wd = warp_n * 20 + nt * 4 + lc;
        uint32_t hw, lw;
        split_pack2(acc[nt][0] * inv0, acc[nt][1] * inv0, hw, lw);
        phs[q0 * PSTR + wd] = hw;
        pls[q0 * PSTR + wd] = lw;
        split_pack2(acc[nt][2] * inv1, acc[nt][3] * inv1, hw, lw);
        phs[q1 * PSTR + wd] = hw;
        pls[q1 * PSTR + wd] = lw;
    }
    __syncthreads();

    // ---- attention weights output: reconstruct hi+lo (coalesced) ----
    if (attn_out) {
        int qrow = warp * 4;
#pragma unroll
        for (int i = 0; i < 4; ++i) {
            int qq = qrow + i;
            int arow = ((b * Hn + h) * Sdim + s0 + qq) * WIN;
#pragma unroll
            for (int j = 0; j < 4; ++j) {
                int w = lane + 32 * j;
                int key = qq + w;
                uint32_t hw = phs[qq * PSTR + (key >> 1)];
                uint32_t lw = pls[qq * PSTR + (key >> 1)];
                attn_out[arow + w] =
                    bf16_half_to_f(hw, key & 1) + bf16_half_to_f(lw, key & 1);
            }
            if (lane == 0) {
                int key = qq + 128;
                uint32_t hw = phs[qq * PSTR + (key >> 1)];
                uint32_t lw = pls[qq * PSTR + (key >> 1)];
                attn_out[arow + 128] =
                    bf16_half_to_f(hw, key & 1) + bf16_half_to_f(lw, key & 1);
            }
        }
    }

    // ---- ctx = P(32x160) @ V(160x32): 10 k16-steps, warp = 16 q x 8 dims ----
    float c[4] = {0.f, 0.f, 0.f, 0.f};
#pragma unroll
    for (int s = 0; s < 10; ++s) {
        uint32_t ah[4], al[4], bh[2], bl[2];
        ah[0] = phs[q0 * PSTR + s * 8 + lc];
        ah[1] = phs[q1 * PSTR + s * 8 + lc];
        ah[2] = phs[q0 * PSTR + s * 8 + lc + 4];
        ah[3] = phs[q1 * PSTR + s * 8 + lc + 4];
        al[0] = pls[q0 * PSTR + s * 8 + lc];
        al[1] = pls[q1 * PSTR + s * 8 + lc];
        al[2] = pls[q0 * PSTR + s * 8 + lc + 4];
        al[3] = pls[q1 * PSTR + s * 8 + lc + 4];
        bh[0] = vhs[(s * 8 + lc) * VSTR + warp_n * 8 + lr];
        bh[1] = vhs[(s * 8 + lc + 4) * VSTR + warp_n * 8 + lr];
        bl[0] = vls[(s * 8 + lc) * VSTR + warp_n * 8 + lr];
        bl[1] = vls[(s * 8 + lc + 4) * VSTR + warp_n * 8 + lr];
        mma_bf16(c, al, bh);
        mma_bf16(c, ah, bl);
        mma_bf16(c, ah, bh);
    }

    // ---- pack ctx to bf16 hi/lo words for the O projection ----
    {
        int pkbase = (b * Sdim) * KW + h * (HD / 2);
        int wd = warp_n * 4 + lc;
        uint32_t hw, lw;
        split_pack2(c[0], c[1], hw, lw);
        ctx_h[pkbase + (s0 + q0) * KW + wd] = hw;
        ctx_l[pkbase + (s0 + q0) * KW + wd] = lw;
        split_pack2(c[2], c[3], hw, lw);
        ctx_h[pkbase + (s0 + q1) * KW + wd] = hw;
        ctx_l[pkbase + (s0 + q1) * KW + wd] = lw;
    }
}

// ---------------------------------------------------------------------------
extern "C" void kernel_launch(void* const* d_in, const int* in_sizes, int n_in,
                              void* d_out, int out_size) {
    const float* x  = (const float*)d_in[0];
    const float* Wq = (const float*)d_in[1];
    const float* bq = (const float*)d_in[2];
    const float* Wk = (const float*)d_in[3];
    const float* bk = (const float*)d_in[4];
    const float* Wv = (const float*)d_in[5];
    const float* bv = (const float*)d_in[6];
    const float* Wo = (const float*)d_in[7];
    const float* bo = (const float*)d_in[8];
    float* out = (float*)d_out;

    uint32_t *xh, *xl, *ch, *cl, *wh, *wl;
    float *q, *k, *v;
    cudaGetSymbolAddress((void**)&xh, g_xh);
    cudaGetSymbolAddress((void**)&xl, g_xl);
    cudaGetSymbolAddress((void**)&q,  g_q);
    cudaGetSymbolAddress((void**)&k,  g_k);
    cudaGetSymbolAddress((void**)&v,  g_v);
    cudaGetSymbolAddress((void**)&ch, g_ch);
    cudaGetSymbolAddress((void**)&cl, g_cl);
    cudaGetSymbolAddress((void**)&wh, g_wh);
    cudaGetSymbolAddress((void**)&wl, g_wl);

    const long OUT_ELEMS  = (long)Bz * Sdim * Edim;                 // 1,048,576
    const long ATTN_ELEMS = (long)Bz * Hn * Sdim * WIN;             // 4,227,072
    float* attn_out = nullptr;
    if ((long)out_size >= OUT_ELEMS + ATTN_ELEMS) attn_out = out + OUT_ELEMS;

    static bool attr_set = false;
    if (!attr_set) {
        cudaFuncSetAttribute(attn_kernel,
                             cudaFuncAttributeMaxDynamicSharedMemorySize,
                             SM_TOT * 4);
        attr_set = true;
    }

    add_pe_pack_kernel<<<MTOK * KW / 256, 256>>>(x, xh, xl);
    pack_w_kernel<<<4 * WPK / 256, 256>>>(Wq, Wk, Wv, Wo, wh, wl);

    // Fused Q/K/V projections: grid.y 0-3 -> Wq, 4-7 -> Wk, 8-11 -> Wv
    gemm_tc_kernel<<<dim3(MTOK / GBM, 12), 128>>>(
        xh, xl, wh, wl, bq, q, bk, k, bv, v);

    attn_kernel<<<dim3(Sdim / 32, Hn, Bz), 256, SM_TOT * 4>>>(
        q, k, v, ch, cl, attn_out);

    // Output projection: grid.y 0-3 -> Wo (index 3 in packed weights)
    gemm_tc_kernel<<<dim3(MTOK / GBM, 4), 128>>>(
        ch, cl, wh + 3 * WPK, wl + 3 * WPK, bo, out, bo, out, bo, out);
}